// round 9
// baseline (speedup 1.0000x reference)
#include <cuda_runtime.h>
#include <math.h>

#define NB 32
#define CH 128
#define HW 4096           // 64*64
#define CNT 131072.0f     // NB*HW, bn population per channel
#define EPS 1e-5f

typedef unsigned long long ull;

// ---------------- scratch (device globals; no mallocs allowed) ----------------
__device__ float g_s  [NB*2*HW];      // channel mean/max planes
__device__ float g_sig[NB*HW];        // spatial-attention sigmoid map
__device__ float g_x2 [NB*CH*HW];     // x * spatial att * channel att
__device__ float g_bufA[NB*CH*HW];    // dw outputs
__device__ float g_bufB[NB*CH*HW];    // mid pw outputs (sep)
__device__ float g_b1 [NB*CH*HW];     // maxpool branch
__device__ float g_b2 [NB*CH*HW];     // avgpool branch
__device__ float g_b4 [NB*CH*HW];     // sep3 branch (pre-bn)
__device__ float g_b5 [NB*CH*HW];     // sep5 branch
__device__ float g_b6 [NB*CH*HW];     // dil3 branch
__device__ float g_b7 [NB*CH*HW];     // dil5 branch
__device__ float g_psum[NB*CH];
__device__ float g_pmax[NB*CH];
__device__ float g_att [NB*CH];
__device__ int   g_nd[CH];
__device__ int   g_winner[CH];
__device__ float g_sum[8*CH];         // bn stats slots
__device__ float g_sq [8*CH];
__device__ float g_WT [6*CH*CH];      // transposed pw weights [ci][co]

// ---------------- tiny helper kernels ----------------
__global__ void k_zero_stats() {
    int i = blockIdx.x*256 + threadIdx.x;
    if (i < 8*CH) { g_sum[i] = 0.f; g_sq[i] = 0.f; }
}

__global__ void k_transw(const float* w0, const float* w1, const float* w2,
                         const float* w3, const float* w4, const float* w5) {
    const float* ws[6] = {w0,w1,w2,w3,w4,w5};
    const float* w = ws[blockIdx.x];
    float* o = g_WT + blockIdx.x*CH*CH;
    for (int i = threadIdx.x; i < CH*CH; i += 256) {
        int ci = i >> 7, co = i & 127;
        o[i] = w[co*CH + ci];
    }
}

// ---------------- stage A: spatial attention ----------------
// per (n,hw): mean & max over channels of original x
__global__ void k_chanstat(const float* __restrict__ x) {
    int idx = blockIdx.x*256 + threadIdx.x;       // n*HW + hw
    if (idx >= NB*HW) return;
    int n = idx >> 12, hw = idx & (HW-1);
    const float* p = x + (size_t)n*CH*HW + hw;
    float s = 0.f, m = -1e30f;
    #pragma unroll 8
    for (int c = 0; c < CH; c++) { float v = p[c*HW]; s += v; m = fmaxf(m, v); }
    g_s[n*2*HW + hw]      = s * (1.f/CH);
    g_s[n*2*HW + HW + hw] = m;
}

// 7x7 conv (2->1 ch, pad 3) + sigmoid. 512 blocks, L2-resident input (1MB).
__global__ void k_saconv(const float* __restrict__ saw) {
    __shared__ float w[98];
    if (threadIdx.x < 98) w[threadIdx.x] = saw[threadIdx.x];
    __syncthreads();
    int n  = blockIdx.x >> 4;
    int hw = (blockIdx.x & 15) * 256 + threadIdx.x;
    int h = hw >> 6, wx = hw & 63;
    const float* sp = g_s + n*2*HW;
    float acc = 0.f;
    #pragma unroll
    for (int ic = 0; ic < 2; ic++)
        #pragma unroll
        for (int kh = 0; kh < 7; kh++) {
            int ih = h + kh - 3;
            if (ih < 0 || ih > 63) continue;
            #pragma unroll
            for (int kw = 0; kw < 7; kw++) {
                int iw = wx + kw - 3;
                if (iw >= 0 && iw <= 63)
                    acc += __ldg(&sp[ic*HW + ih*64 + iw]) * w[ic*49 + kh*7 + kw];
            }
        }
    g_sig[n*HW + hw] = 1.f / (1.f + __expf(-acc));
}

// stats of x1 = x*sig over HW per (n,c)  (x1 not materialized)
__global__ void k_x1red(const float* __restrict__ x) {
    int n = blockIdx.x >> 7, c = blockIdx.x & 127;
    size_t base = ((size_t)n*CH + c)*HW;
    const float* sg = g_sig + n*HW;
    float s = 0.f, m = -1e30f;
    for (int i = threadIdx.x; i < HW; i += 256) {
        float v = x[base+i] * sg[i];
        s += v; m = fmaxf(m, v);
    }
    __shared__ float rs[256], rm[256];
    rs[threadIdx.x] = s; rm[threadIdx.x] = m; __syncthreads();
    for (int o = 128; o > 0; o >>= 1) {
        if (threadIdx.x < o) {
            rs[threadIdx.x] += rs[threadIdx.x + o];
            rm[threadIdx.x] = fmaxf(rm[threadIdx.x], rm[threadIdx.x + o]);
        }
        __syncthreads();
    }
    if (threadIdx.x == 0) { g_psum[n*CH+c] = rs[0]; g_pmax[n*CH+c] = rm[0]; }
}

// ---------------- stage B: channel attention MLP ----------------
__global__ void k_att(const float* __restrict__ fc1, const float* __restrict__ fc2) {
    int n = blockIdx.x, t = threadIdx.x;   // 128 threads
    __shared__ float m[CH], mx[CH], hm[64], hx[64];
    m[t]  = g_psum[n*CH+t] * (1.f/HW);
    mx[t] = g_pmax[n*CH+t];
    __syncthreads();
    if (t < 64) {
        float a = 0.f, b = 0.f;
        for (int c = 0; c < CH; c++) { float w = fc1[t*CH+c]; a += w*m[c]; b += w*mx[c]; }
        hm[t] = fmaxf(a, 0.f); hx[t] = fmaxf(b, 0.f);
    }
    __syncthreads();
    float a = 0.f, b = 0.f;
    for (int k = 0; k < 64; k++) { float w = fc2[t*64+k]; a += w*hm[k]; b += w*hx[k]; }
    g_att[n*CH+t] = 1.f / (1.f + __expf(-(a + b)));
}

// slist sum, top-k ranks, num_dict, winner (last-wins scatter)
__global__ void k_topk(const int* __restrict__ perm) {
    int c = threadIdx.x;   // 128 threads
    __shared__ float sl[CH];
    float s = 0.f;
    for (int n = 0; n < NB; n++) s += g_att[n*CH + c];
    sl[c] = s; __syncthreads();
    float v = sl[c];
    int rank = 0;
    for (int d = 0; d < CH; d++) { float u = sl[d]; rank += (u > v) || (u == v && d < c); }
    if (rank < 96) g_nd[rank] = c;
    if (c < 32) g_nd[96 + c] = perm[c];
    int win;
    if (c < 32) {
        int inv = 0;
        for (int i = 0; i < 32; i++) if (perm[i] == c) inv = i;
        win = 96 + inv;                 // perm positions are last -> always win
    } else {
        win = (rank < 96) ? rank : -1;
    }
    g_winner[c] = win;
}

// x2 = x * sig * att
__global__ void k_x2(const float* __restrict__ x) {
    int b = blockIdx.x;     // n*CH + c
    int n = b >> 7;
    float a = g_att[b];
    const float* sg = g_sig + n*HW;
    size_t base = (size_t)b * HW;
    for (int i = threadIdx.x; i < HW; i += 256)
        g_x2[base+i] = x[base+i] * sg[i] * a;
}

// ---------------- stage C: branches ----------------
// fused max & avg 3x3 pool on xt (= x2 gathered by nd), with bn stats slots 0/1
__global__ void k_pool() {
    __shared__ float pl[HW];
    int n = blockIdx.x >> 7, j = blockIdx.x & 127;
    int cin = g_nd[j];
    size_t ib = ((size_t)n*CH + cin)*HW, ob = ((size_t)n*CH + j)*HW;
    for (int i = threadIdx.x; i < HW; i += 256) pl[i] = g_x2[ib+i];
    __syncthreads();
    float s1 = 0.f, q1 = 0.f, s2 = 0.f, q2 = 0.f;
    for (int i = threadIdx.x; i < HW; i += 256) {
        int h = i >> 6, w = i & 63;
        int h0 = max(h-1,0), h1 = min(h+1,63), w0 = max(w-1,0), w1 = min(w+1,63);
        float mx = -1e30f, sm = 0.f;
        for (int hh = h0; hh <= h1; hh++)
            for (int ww = w0; ww <= w1; ww++) {
                float v = pl[hh*64+ww];
                mx = fmaxf(mx, v); sm += v;
            }
        float av = sm / (float)((h1-h0+1)*(w1-w0+1));
        g_b1[ob+i] = mx; g_b2[ob+i] = av;
        s1 += mx; q1 += mx*mx; s2 += av; q2 += av*av;
    }
    __syncthreads();
    pl[threadIdx.x] = s1; pl[256+threadIdx.x] = q1;
    pl[512+threadIdx.x] = s2; pl[768+threadIdx.x] = q2;
    __syncthreads();
    for (int o = 128; o > 0; o >>= 1) {
        if (threadIdx.x < o) {
            pl[threadIdx.x]     += pl[threadIdx.x+o];
            pl[256+threadIdx.x] += pl[256+threadIdx.x+o];
            pl[512+threadIdx.x] += pl[512+threadIdx.x+o];
            pl[768+threadIdx.x] += pl[768+threadIdx.x+o];
        }
        __syncthreads();
    }
    if (threadIdx.x == 0) {
        atomicAdd(&g_sum[0*CH+j], pl[0]);   atomicAdd(&g_sq[0*CH+j], pl[256]);
        atomicAdd(&g_sum[1*CH+j], pl[512]); atomicAdd(&g_sq[1*CH+j], pl[768]);
    }
}

// depthwise conv; pre-op: slot<0 -> relu(in), slot>=0 -> relu(bn_slot(in))
// nd != null -> gather input channel through nd (first-stage dw reading x2)
template<int KS, int DIL>
__global__ void k_dw(const float* __restrict__ in, const float* __restrict__ dwW,
                     float* __restrict__ out, const int* __restrict__ nd, int slot) {
    __shared__ float pl[HW];
    __shared__ float wt[KS*KS];
    __shared__ float bnp[2];
    int n = blockIdx.x >> 7, j = blockIdx.x & 127;
    int cin = nd ? nd[j] : j;
    if (threadIdx.x == 0) {
        if (slot >= 0) {
            float mean = g_sum[slot*CH + j] / CNT;
            float var  = g_sq [slot*CH + j] / CNT - mean*mean;
            bnp[0] = mean; bnp[1] = rsqrtf(var + EPS);
        } else { bnp[0] = 0.f; bnp[1] = 1.f; }
    }
    if (threadIdx.x < KS*KS) wt[threadIdx.x] = dwW[j*KS*KS + threadIdx.x];
    __syncthreads();
    float mean = bnp[0], rstd = bnp[1];
    size_t ib = ((size_t)n*CH + cin)*HW;
    for (int i = threadIdx.x; i < HW; i += 256) {
        float v = (in[ib+i] - mean) * rstd;
        pl[i] = fmaxf(v, 0.f);
    }
    __syncthreads();
    size_t ob = ((size_t)n*CH + j)*HW;
    constexpr int R = DIL * (KS/2);
    for (int i = threadIdx.x; i < HW; i += 256) {
        int h = i >> 6, w = i & 63;
        float acc = 0.f;
        #pragma unroll
        for (int kh = 0; kh < KS; kh++) {
            int ih = h - R + kh*DIL;
            if (ih < 0 || ih > 63) continue;
            #pragma unroll
            for (int kw = 0; kw < KS; kw++) {
                int iw = w - R + kw*DIL;
                if (iw >= 0 && iw <= 63)
                    acc += pl[ih*64 + iw] * wt[kh*KS + kw];
            }
        }
        out[ob+i] = acc;
    }
}

// pointwise 1x1 conv = GEMM with packed fp32x2 FMA:
//   out[co,p] = sum_ci WT[ci][co] * in[ci,p]
// tile 128co x 128p per block, 4co x 16p microtile/thread (32 packed accs).
__global__ void __launch_bounds__(256) k_pw(const float* __restrict__ in,
                                            const float* __restrict__ wt,
                                            float* __restrict__ out, int slot) {
    extern __shared__ float smem[];
    float* sW = smem;            // 128*128
    float* sI = smem + CH*CH;    // 128*128
    int n = blockIdx.x >> 5;
    int pbase = (blockIdx.x & 31) * 128;
    for (int i = threadIdx.x; i < CH*CH/4; i += 256)
        ((float4*)sW)[i] = ((const float4*)wt)[i];
    for (int i = threadIdx.x; i < CH*128/4; i += 256) {
        int ci = i >> 5, p4 = i & 31;
        ((float4*)sI)[i] = *(const float4*)(in + ((size_t)n*CH + ci)*HW + pbase + p4*4);
    }
    __syncthreads();
    int ty = threadIdx.x >> 3, tx = threadIdx.x & 7;
    int co0 = ty*4, p0 = tx*16;
    ull acc[4][8];
    #pragma unroll
    for (int i = 0; i < 4; i++)
        #pragma unroll
        for (int k = 0; k < 8; k++) acc[i][k] = 0ULL;   // two packed 0.0f
    #pragma unroll 2
    for (int ci = 0; ci < CH; ci++) {
        float4 wv = *(const float4*)&sW[ci*CH + co0];
        ull w2[4];
        asm("mov.b64 %0, {%1, %1};" : "=l"(w2[0]) : "f"(wv.x));
        asm("mov.b64 %0, {%1, %1};" : "=l"(w2[1]) : "f"(wv.y));
        asm("mov.b64 %0, {%1, %1};" : "=l"(w2[2]) : "f"(wv.z));
        asm("mov.b64 %0, {%1, %1};" : "=l"(w2[3]) : "f"(wv.w));
        const ulonglong2* ap = (const ulonglong2*)&sI[ci*128 + p0];
        ull av[8];
        #pragma unroll
        for (int k = 0; k < 4; k++) {
            ulonglong2 t = ap[k];
            av[k*2] = t.x; av[k*2+1] = t.y;
        }
        #pragma unroll
        for (int i = 0; i < 4; i++)
            #pragma unroll
            for (int k = 0; k < 8; k++)
                asm("fma.rn.f32x2 %0, %1, %2, %0;"
                    : "+l"(acc[i][k]) : "l"(w2[i]), "l"(av[k]));
    }
    #pragma unroll
    for (int i = 0; i < 4; i++) {
        int co = co0 + i;
        float* op = out + ((size_t)n*CH + co)*HW + pbase + p0;
        // store 16 floats = 4x STG.128 (two packed regs each)
        #pragma unroll
        for (int k = 0; k < 4; k++)
            asm volatile("st.global.v2.u64 [%0], {%1, %2};"
                         :: "l"(op + k*4), "l"(acc[i][k*2]), "l"(acc[i][k*2+1]));
        // bn stats: packed accumulate then unpack once
        ull s2 = 0ULL, q2 = 0ULL;
        #pragma unroll
        for (int k = 0; k < 8; k++) {
            asm("add.rn.f32x2 %0, %0, %1;" : "+l"(s2) : "l"(acc[i][k]));
            asm("fma.rn.f32x2 %0, %1, %1, %0;" : "+l"(q2) : "l"(acc[i][k]));
        }
        float slo, shi, qlo, qhi;
        asm("mov.b64 {%0, %1}, %2;" : "=f"(slo), "=f"(shi) : "l"(s2));
        asm("mov.b64 {%0, %1}, %2;" : "=f"(qlo), "=f"(qhi) : "l"(q2));
        float s = slo + shi, q = qlo + qhi;
        for (int o = 4; o > 0; o >>= 1) {
            s += __shfl_down_sync(0xffffffffu, s, o, 8);
            q += __shfl_down_sync(0xffffffffu, q, o, 8);
        }
        if (tx == 0) {
            atomicAdd(&g_sum[slot*CH + co], s);
            atomicAdd(&g_sq [slot*CH + co], q);
        }
    }
}

// ---------------- final: weighted branch sum (+bn) and scatter ----------------
__global__ void k_final(const float* __restrict__ wts, float* __restrict__ out) {
    int n = blockIdx.x >> 7, c = blockIdx.x & 127;
    int win = g_winner[c];
    size_t ob = ((size_t)n*CH + c)*HW;
    if (win < 0) {
        for (int i = threadIdx.x; i < HW; i += 256) out[ob+i] = g_x2[ob+i];
        return;
    }
    int j = win;
    __shared__ float P[12];
    __shared__ float W[8];
    if (threadIdx.x < 8) W[threadIdx.x] = wts[threadIdx.x];
    if (threadIdx.x == 0) {
        const int slots[6] = {0,1,3,5,6,7};
        for (int q = 0; q < 6; q++) {
            float mean = g_sum[slots[q]*CH + j] / CNT;
            float var  = g_sq [slots[q]*CH + j] / CNT - mean*mean;
            P[q*2] = mean; P[q*2+1] = rsqrtf(var + EPS);
        }
    }
    __syncthreads();
    size_t jb = ((size_t)n*CH + j)*HW;
    for (int i = threadIdx.x; i < HW; i += 256) {
        float r = W[3]*g_x2[ob+i];
        r += W[1]*((g_b1[jb+i]-P[0]) *P[1]);
        r += W[2]*((g_b2[jb+i]-P[2]) *P[3]);
        r += W[4]*((g_b4[jb+i]-P[4]) *P[5]);
        r += W[5]*((g_b5[jb+i]-P[6]) *P[7]);
        r += W[6]*((g_b6[jb+i]-P[8]) *P[9]);
        r += W[7]*((g_b7[jb+i]-P[10])*P[11]);
        out[ob+i] = r;
    }
}

// ---------------- launch ----------------
extern "C" void kernel_launch(void* const* d_in, const int* in_sizes, int n_in,
                              void* d_out, int out_size) {
    const float* x    = (const float*)d_in[0];
    const float* wts  = (const float*)d_in[1];
    const float* fc1  = (const float*)d_in[2];
    const float* fc2  = (const float*)d_in[3];
    const float* saw  = (const float*)d_in[4];
    const float* s3d1 = (const float*)d_in[5];
    const float* s3p1 = (const float*)d_in[6];
    const float* s3d2 = (const float*)d_in[7];
    const float* s3p2 = (const float*)d_in[8];
    const float* s5d1 = (const float*)d_in[9];
    const float* s5p1 = (const float*)d_in[10];
    const float* s5d2 = (const float*)d_in[11];
    const float* s5p2 = (const float*)d_in[12];
    const float* d3d  = (const float*)d_in[13];
    const float* d3p  = (const float*)d_in[14];
    const float* d5d  = (const float*)d_in[15];
    const float* d5p  = (const float*)d_in[16];
    const int*   perm = (const int*)d_in[17];
    float* out = (float*)d_out;

    // Resolve real device addresses of __device__ globals (host shadow trap).
    float *p_x2, *p_bufA, *p_bufB, *p_b4, *p_b5, *p_b6, *p_b7, *p_WT;
    int   *p_nd;
    cudaGetSymbolAddress((void**)&p_x2,  g_x2);
    cudaGetSymbolAddress((void**)&p_bufA, g_bufA);
    cudaGetSymbolAddress((void**)&p_bufB, g_bufB);
    cudaGetSymbolAddress((void**)&p_b4,  g_b4);
    cudaGetSymbolAddress((void**)&p_b5,  g_b5);
    cudaGetSymbolAddress((void**)&p_b6,  g_b6);
    cudaGetSymbolAddress((void**)&p_b7,  g_b7);
    cudaGetSymbolAddress((void**)&p_WT,  g_WT);
    cudaGetSymbolAddress((void**)&p_nd,  g_nd);

    const int PW_SMEM = (CH*CH + CH*128) * (int)sizeof(float); // 128 KB
    cudaFuncSetAttribute(k_pw, cudaFuncAttributeMaxDynamicSharedMemorySize, PW_SMEM);

    k_zero_stats<<<4, 256>>>();
    k_transw<<<6, 256>>>(s3p1, s3p2, s5p1, s5p2, d3p, d5p);

    k_chanstat<<<(NB*HW)/256, 256>>>(x);
    k_saconv<<<NB*16, 256>>>(saw);
    k_x1red<<<NB*CH, 256>>>(x);
    k_att<<<NB, 128>>>(fc1, fc2);
    k_topk<<<1, 128>>>(perm);
    k_x2<<<NB*CH, 256>>>(x);

    k_pool<<<NB*CH, 256>>>();

    // sep3: relu -> dw3 -> pw1(stats s2) -> bn+relu -> dw3 -> pw2(stats s3)
    k_dw<3,1><<<NB*CH, 256>>>(p_x2,  s3d1, p_bufA, p_nd, -1);
    k_pw<<<NB*32, 256, PW_SMEM>>>(p_bufA, p_WT + 0*CH*CH, p_bufB, 2);
    k_dw<3,1><<<NB*CH, 256>>>(p_bufB, s3d2, p_bufA, (const int*)nullptr, 2);
    k_pw<<<NB*32, 256, PW_SMEM>>>(p_bufA, p_WT + 1*CH*CH, p_b4, 3);

    // sep5
    k_dw<5,1><<<NB*CH, 256>>>(p_x2,  s5d1, p_bufA, p_nd, -1);
    k_pw<<<NB*32, 256, PW_SMEM>>>(p_bufA, p_WT + 2*CH*CH, p_bufB, 4);
    k_dw<5,1><<<NB*CH, 256>>>(p_bufB, s5d2, p_bufA, (const int*)nullptr, 4);
    k_pw<<<NB*32, 256, PW_SMEM>>>(p_bufA, p_WT + 3*CH*CH, p_b5, 5);

    // dil3 (3x3 dil2 pad2)
    k_dw<3,2><<<NB*CH, 256>>>(p_x2, d3d, p_bufA, p_nd, -1);
    k_pw<<<NB*32, 256, PW_SMEM>>>(p_bufA, p_WT + 4*CH*CH, p_b6, 6);

    // dil5 (5x5 dil2 pad4)
    k_dw<5,2><<<NB*CH, 256>>>(p_x2, d5d, p_bufA, p_nd, -1);
    k_pw<<<NB*32, 256, PW_SMEM>>>(p_bufA, p_WT + 5*CH*CH, p_b7, 7);

    k_final<<<NB*CH, 256>>>(wts, out);
}

// round 10
// speedup vs baseline: 1.5848x; 1.5848x over previous
#include <cuda_runtime.h>
#include <math.h>

#define NB 32
#define CH 128
#define HW 4096           // 64*64
#define CNT 131072.0f     // NB*HW, bn population per channel
#define EPS 1e-5f
#define SP 72             // padded plane stride (PAD=4 halo each side)
#define PPN (SP*SP)       // 5184

// ---------------- scratch (device globals; no mallocs allowed) ----------------
__device__ float g_s  [NB*2*HW];      // channel mean/max planes
__device__ float g_sig[NB*HW];        // spatial-attention sigmoid map
__device__ float g_x2 [NB*CH*HW];     // x * spatial att * channel att
__device__ float g_bufA[NB*CH*HW];    // sep3 dw / scratch
__device__ float g_bufB[NB*CH*HW];    // sep5 dw / scratch
__device__ float g_b1 [NB*CH*HW];     // maxpool branch
__device__ float g_b2 [NB*CH*HW];     // avgpool branch
__device__ float g_b4 [NB*CH*HW];     // sep3 branch
__device__ float g_b5 [NB*CH*HW];     // sep5 branch
__device__ float g_b6 [NB*CH*HW];     // dil3 branch
__device__ float g_b7 [NB*CH*HW];     // dil5 branch
__device__ float g_psum[NB*CH];
__device__ float g_pmax[NB*CH];
__device__ float g_att [NB*CH];
__device__ int   g_nd[CH];
__device__ int   g_winner[CH];
__device__ float g_sum[8*CH];         // bn stats slots
__device__ float g_sq [8*CH];
__device__ float g_WT [6*CH*CH];      // transposed pw weights [ci][co]

// ---------------- tiny helper kernels ----------------
__global__ void k_zero_stats() {
    int i = blockIdx.x*256 + threadIdx.x;
    if (i < 8*CH) { g_sum[i] = 0.f; g_sq[i] = 0.f; }
}

__global__ void k_transw(const float* w0, const float* w1, const float* w2,
                         const float* w3, const float* w4, const float* w5) {
    const float* ws[6] = {w0,w1,w2,w3,w4,w5};
    const float* w = ws[blockIdx.x];
    float* o = g_WT + blockIdx.x*CH*CH;
    for (int i = threadIdx.x; i < CH*CH; i += 256) {
        int ci = i >> 7, co = i & 127;
        o[i] = w[co*CH + ci];
    }
}

// ---------------- stage A: spatial attention ----------------
__global__ void k_chanstat(const float* __restrict__ x) {
    int idx = blockIdx.x*256 + threadIdx.x;       // n*HW + hw
    if (idx >= NB*HW) return;
    int n = idx >> 12, hw = idx & (HW-1);
    const float* p = x + (size_t)n*CH*HW + hw;
    float s = 0.f, m = -1e30f;
    #pragma unroll 8
    for (int c = 0; c < CH; c++) { float v = p[c*HW]; s += v; m = fmaxf(m, v); }
    g_s[n*2*HW + hw]      = s * (1.f/CH);
    g_s[n*2*HW + HW + hw] = m;
}

// 7x7 conv (2->1 ch, pad 3) + sigmoid. 512 blocks, L2-resident input.
__global__ void k_saconv(const float* __restrict__ saw) {
    __shared__ float w[98];
    if (threadIdx.x < 98) w[threadIdx.x] = saw[threadIdx.x];
    __syncthreads();
    int n  = blockIdx.x >> 4;
    int hw = (blockIdx.x & 15) * 256 + threadIdx.x;
    int h = hw >> 6, wx = hw & 63;
    const float* sp = g_s + n*2*HW;
    float acc = 0.f;
    #pragma unroll
    for (int ic = 0; ic < 2; ic++)
        #pragma unroll
        for (int kh = 0; kh < 7; kh++) {
            int ih = h + kh - 3;
            if (ih < 0 || ih > 63) continue;
            #pragma unroll
            for (int kw = 0; kw < 7; kw++) {
                int iw = wx + kw - 3;
                if (iw >= 0 && iw <= 63)
                    acc += __ldg(&sp[ic*HW + ih*64 + iw]) * w[ic*49 + kh*7 + kw];
            }
        }
    g_sig[n*HW + hw] = 1.f / (1.f + __expf(-acc));
}

// stats of x1 = x*sig over HW per (n,c)  (x1 not materialized)
__global__ void k_x1red(const float* __restrict__ x) {
    int n = blockIdx.x >> 7, c = blockIdx.x & 127;
    size_t base = ((size_t)n*CH + c)*HW;
    const float* sg = g_sig + n*HW;
    float s = 0.f, m = -1e30f;
    for (int i = threadIdx.x; i < HW; i += 256) {
        float v = x[base+i] * sg[i];
        s += v; m = fmaxf(m, v);
    }
    __shared__ float rs[256], rm[256];
    rs[threadIdx.x] = s; rm[threadIdx.x] = m; __syncthreads();
    for (int o = 128; o > 0; o >>= 1) {
        if (threadIdx.x < o) {
            rs[threadIdx.x] += rs[threadIdx.x + o];
            rm[threadIdx.x] = fmaxf(rm[threadIdx.x], rm[threadIdx.x + o]);
        }
        __syncthreads();
    }
    if (threadIdx.x == 0) { g_psum[n*CH+c] = rs[0]; g_pmax[n*CH+c] = rm[0]; }
}

// ---------------- stage B: channel attention MLP ----------------
__global__ void k_att(const float* __restrict__ fc1, const float* __restrict__ fc2) {
    int n = blockIdx.x, t = threadIdx.x;   // 128 threads
    __shared__ float m[CH], mx[CH], hm[64], hx[64];
    m[t]  = g_psum[n*CH+t] * (1.f/HW);
    mx[t] = g_pmax[n*CH+t];
    __syncthreads();
    if (t < 64) {
        float a = 0.f, b = 0.f;
        for (int c = 0; c < CH; c++) { float w = fc1[t*CH+c]; a += w*m[c]; b += w*mx[c]; }
        hm[t] = fmaxf(a, 0.f); hx[t] = fmaxf(b, 0.f);
    }
    __syncthreads();
    float a = 0.f, b = 0.f;
    for (int k = 0; k < 64; k++) { float w = fc2[t*64+k]; a += w*hm[k]; b += w*hx[k]; }
    g_att[n*CH+t] = 1.f / (1.f + __expf(-(a + b)));
}

// slist sum, top-k ranks, num_dict, winner (last-wins scatter)
__global__ void k_topk(const int* __restrict__ perm) {
    int c = threadIdx.x;   // 128 threads
    __shared__ float sl[CH];
    float s = 0.f;
    for (int n = 0; n < NB; n++) s += g_att[n*CH + c];
    sl[c] = s; __syncthreads();
    float v = sl[c];
    int rank = 0;
    for (int d = 0; d < CH; d++) { float u = sl[d]; rank += (u > v) || (u == v && d < c); }
    if (rank < 96) g_nd[rank] = c;
    if (c < 32) g_nd[96 + c] = perm[c];
    int win;
    if (c < 32) {
        int inv = 0;
        for (int i = 0; i < 32; i++) if (perm[i] == c) inv = i;
        win = 96 + inv;                 // perm positions are last -> always win
    } else {
        win = (rank < 96) ? rank : -1;
    }
    g_winner[c] = win;
}

// x2 = x * sig * att  (float4)
__global__ void k_x2(const float* __restrict__ x) {
    int b = blockIdx.x;     // n*CH + c
    int n = b >> 7;
    float a = g_att[b];
    const float4* sg = (const float4*)(g_sig + n*HW);
    const float4* xi = (const float4*)(x + (size_t)b*HW);
    float4*       xo = (float4*)(g_x2 + (size_t)b*HW);
    for (int i = threadIdx.x; i < HW/4; i += 256) {
        float4 v = xi[i], s = sg[i];
        v.x *= s.x*a; v.y *= s.y*a; v.z *= s.z*a; v.w *= s.w*a;
        xo[i] = v;
    }
}

// ---------------- depthwise quad helper ----------------
// padded plane (SP=72, origin (4,4), zero halo). 4 consecutive px per call.
template<int KS, int DIL>
__device__ __forceinline__ void dw_quad(const float* __restrict__ pl, int h, int w0,
                                        const float* __restrict__ wt, float4* outv) {
    constexpr int R2 = (KS/2)*DIL;      // <= 4 for all our convs
    float a0 = 0.f, a1 = 0.f, a2 = 0.f, a3 = 0.f;
    #pragma unroll
    for (int kh = 0; kh < KS; kh++) {
        int ph = h + 4 + (kh - KS/2)*DIL;
        const float4* rp = (const float4*)&pl[ph*SP + w0];   // covers rel [-4, +8)
        float buf[12];
        #pragma unroll
        for (int l = 0; l < 3; l++) {
            float4 t = rp[l];
            buf[l*4+0]=t.x; buf[l*4+1]=t.y; buf[l*4+2]=t.z; buf[l*4+3]=t.w;
        }
        #pragma unroll
        for (int kw = 0; kw < KS; kw++) {
            float wv = wt[kh*KS + kw];
            constexpr int base = 4 - R2;       // rel index of kw=0 into buf
            int b = base + kw*DIL;
            a0 += buf[b+0]*wv; a1 += buf[b+1]*wv; a2 += buf[b+2]*wv; a3 += buf[b+3]*wv;
        }
    }
    *outv = make_float4(a0, a1, a2, a3);
}

// ---------------- stage-1 fusion: gather + pool(max/avg + stats) + 4 first dws ----
__global__ void __launch_bounds__(256) k_stage1(
        const float* __restrict__ w3, const float* __restrict__ w5,
        const float* __restrict__ wd3, const float* __restrict__ wd5) {
    __shared__ float raw[HW];
    __shared__ float pp[PPN];
    __shared__ float red[1024];
    __shared__ float sw3[9], sw5[25], swd3[9], swd5[25];
    int n = blockIdx.x >> 7, j = blockIdx.x & 127;
    int t = threadIdx.x;
    int cin = g_nd[j];
    if (t < 9)  sw3[t]  = w3[j*9 + t];
    if (t < 25) sw5[t]  = w5[j*25 + t];
    if (t >= 32 && t < 41)  swd3[t-32] = wd3[j*9 + (t-32)];
    if (t >= 64 && t < 89)  swd5[t-64] = wd5[j*25 + (t-64)];
    // zero padded plane
    for (int i = t; i < PPN/4; i += 256) ((float4*)pp)[i] = make_float4(0,0,0,0);
    __syncthreads();
    // load gathered plane + relu into padded
    const float4* in4 = (const float4*)(g_x2 + ((size_t)n*CH + cin)*HW);
    for (int q = t; q < 1024; q += 256) {
        float4 v = in4[q];
        ((float4*)raw)[q] = v;
        int h = q >> 4, c4 = (q & 15) * 4;
        float4 r = make_float4(fmaxf(v.x,0.f), fmaxf(v.y,0.f), fmaxf(v.z,0.f), fmaxf(v.w,0.f));
        *(float4*)&pp[(h+4)*SP + c4 + 4] = r;
    }
    __syncthreads();

    size_t ob = ((size_t)n*CH + j)*HW;
    // pool (reads raw, scalar with bounds), accumulate bn stats slots 0/1
    float s1 = 0.f, q1 = 0.f, s2 = 0.f, q2 = 0.f;
    for (int i = t; i < HW; i += 256) {
        int h = i >> 6, w = i & 63;
        int h0 = max(h-1,0), h1 = min(h+1,63), w0 = max(w-1,0), w1 = min(w+1,63);
        float mx = -1e30f, sm = 0.f;
        for (int hh = h0; hh <= h1; hh++)
            for (int ww = w0; ww <= w1; ww++) {
                float v = raw[hh*64+ww];
                mx = fmaxf(mx, v); sm += v;
            }
        float av = sm / (float)((h1-h0+1)*(w1-w0+1));
        g_b1[ob+i] = mx; g_b2[ob+i] = av;
        s1 += mx; q1 += mx*mx; s2 += av; q2 += av*av;
    }
    red[t] = s1; red[256+t] = q1; red[512+t] = s2; red[768+t] = q2;
    __syncthreads();
    for (int o = 128; o > 0; o >>= 1) {
        if (t < o) {
            red[t]     += red[t+o];
            red[256+t] += red[256+t+o];
            red[512+t] += red[512+t+o];
            red[768+t] += red[768+t+o];
        }
        __syncthreads();
    }
    if (t == 0) {
        atomicAdd(&g_sum[0*CH+j], red[0]);   atomicAdd(&g_sq[0*CH+j], red[256]);
        atomicAdd(&g_sum[1*CH+j], red[512]); atomicAdd(&g_sq[1*CH+j], red[768]);
    }
    // four first-stage depthwise convs on relu plane
    for (int q = t; q < 1024; q += 256) {
        int h = q >> 4, w0 = (q & 15) * 4;
        float4 o4;
        dw_quad<3,1>(pp, h, w0, sw3,  &o4); *(float4*)&g_bufA[ob + h*64 + w0] = o4;
        dw_quad<5,1>(pp, h, w0, sw5,  &o4); *(float4*)&g_bufB[ob + h*64 + w0] = o4;
        dw_quad<3,2>(pp, h, w0, swd3, &o4); *(float4*)&g_b6 [ob + h*64 + w0] = o4;
        dw_quad<5,2>(pp, h, w0, swd5, &o4); *(float4*)&g_b7 [ob + h*64 + w0] = o4;
    }
}

// second-stage dw: in -> bn(slot)+relu -> dw(KS, dil1) -> out  (no gather)
template<int KS>
__global__ void __launch_bounds__(256) k_dw2(const float* __restrict__ in,
                                             const float* __restrict__ dwW,
                                             float* __restrict__ out, int slot) {
    __shared__ float pp[PPN];
    __shared__ float wt[KS*KS];
    int n = blockIdx.x >> 7, j = blockIdx.x & 127;
    int t = threadIdx.x;
    if (t < KS*KS) wt[t] = dwW[j*KS*KS + t];
    float mean = g_sum[slot*CH + j] / CNT;
    float var  = g_sq [slot*CH + j] / CNT - mean*mean;
    float rstd = rsqrtf(var + EPS);
    for (int i = t; i < PPN/4; i += 256) ((float4*)pp)[i] = make_float4(0,0,0,0);
    __syncthreads();
    const float4* in4 = (const float4*)(in + ((size_t)n*CH + j)*HW);
    for (int q = t; q < 1024; q += 256) {
        float4 v = in4[q];
        int h = q >> 4, c4 = (q & 15) * 4;
        float4 r = make_float4(fmaxf((v.x-mean)*rstd, 0.f), fmaxf((v.y-mean)*rstd, 0.f),
                               fmaxf((v.z-mean)*rstd, 0.f), fmaxf((v.w-mean)*rstd, 0.f));
        *(float4*)&pp[(h+4)*SP + c4 + 4] = r;
    }
    __syncthreads();
    size_t ob = ((size_t)n*CH + j)*HW;
    for (int q = t; q < 1024; q += 256) {
        int h = q >> 4, w0 = (q & 15) * 4;
        float4 o4;
        dw_quad<KS,1>(pp, h, w0, wt, &o4);
        *(float4*)&out[ob + h*64 + w0] = o4;
    }
}

// pointwise 1x1 conv = GEMM: out[co,p] = sum_ci WT[ci][co] * in[ci,p]
// tile 128co x 64p per block, 4x8 microtile/thread. bn stats into slot.
// In-place safe: block stages its p-tile to smem before any store.
__global__ void __launch_bounds__(256) k_pw(const float* __restrict__ in,
                                            const float* __restrict__ wt,
                                            float* __restrict__ out, int slot) {
    extern __shared__ float smem[];
    float* sW = smem;           // 128*128
    float* sI = smem + CH*CH;   // 128*64
    int n = blockIdx.x >> 6;
    int pbase = (blockIdx.x & 63) * 64;
    for (int i = threadIdx.x; i < CH*CH/4; i += 256)
        ((float4*)sW)[i] = ((const float4*)wt)[i];
    for (int i = threadIdx.x; i < CH*64/4; i += 256) {
        int ci = i >> 4, p4 = i & 15;
        ((float4*)sI)[i] = *(const float4*)(in + ((size_t)n*CH + ci)*HW + pbase + p4*4);
    }
    __syncthreads();
    int ty = threadIdx.x >> 3, tx = threadIdx.x & 7;
    int co0 = ty*4, p0 = tx*8;
    float acc[4][8];
    #pragma unroll
    for (int i = 0; i < 4; i++)
        #pragma unroll
        for (int k = 0; k < 8; k++) acc[i][k] = 0.f;
    #pragma unroll 4
    for (int ci = 0; ci < CH; ci++) {
        float wv[4], av[8];
        *(float4*)&wv[0] = *(const float4*)&sW[ci*CH + co0];
        *(float4*)&av[0] = *(const float4*)&sI[ci*64 + p0];
        *(float4*)&av[4] = *(const float4*)&sI[ci*64 + p0 + 4];
        #pragma unroll
        for (int i = 0; i < 4; i++)
            #pragma unroll
            for (int k = 0; k < 8; k++) acc[i][k] += wv[i]*av[k];
    }
    #pragma unroll
    for (int i = 0; i < 4; i++) {
        int co = co0 + i;
        float* op = &out[((size_t)n*CH + co)*HW + pbase + p0];
        *(float4*)&op[0] = *(float4*)&acc[i][0];
        *(float4*)&op[4] = *(float4*)&acc[i][4];
        float s = 0.f, q = 0.f;
        #pragma unroll
        for (int k = 0; k < 8; k++) { s += acc[i][k]; q += acc[i][k]*acc[i][k]; }
        for (int o = 4; o > 0; o >>= 1) {
            s += __shfl_down_sync(0xffffffffu, s, o, 8);
            q += __shfl_down_sync(0xffffffffu, q, o, 8);
        }
        if (tx == 0) {
            atomicAdd(&g_sum[slot*CH + co], s);
            atomicAdd(&g_sq [slot*CH + co], q);
        }
    }
}

// ---------------- final: weighted branch sum (+bn) and scatter ----------------
__global__ void k_final(const float* __restrict__ wts, float* __restrict__ out) {
    int n = blockIdx.x >> 7, c = blockIdx.x & 127;
    int win = g_winner[c];
    size_t ob = ((size_t)n*CH + c)*HW;
    if (win < 0) {
        float4* o4 = (float4*)(out + ob);
        const float4* x4 = (const float4*)(g_x2 + ob);
        for (int i = threadIdx.x; i < HW/4; i += 256) o4[i] = x4[i];
        return;
    }
    int j = win;
    __shared__ float P[12];
    __shared__ float W[8];
    if (threadIdx.x < 8) W[threadIdx.x] = wts[threadIdx.x];
    if (threadIdx.x == 0) {
        const int slots[6] = {0,1,3,5,6,7};
        for (int q = 0; q < 6; q++) {
            float mean = g_sum[slots[q]*CH + j] / CNT;
            float var  = g_sq [slots[q]*CH + j] / CNT - mean*mean;
            P[q*2] = mean; P[q*2+1] = rsqrtf(var + EPS);
        }
    }
    __syncthreads();
    size_t jb = ((size_t)n*CH + j)*HW;
    const float4* px2 = (const float4*)(g_x2 + ob);
    const float4* p1 = (const float4*)(g_b1 + jb);
    const float4* p2 = (const float4*)(g_b2 + jb);
    const float4* p4 = (const float4*)(g_b4 + jb);
    const float4* p5 = (const float4*)(g_b5 + jb);
    const float4* p6 = (const float4*)(g_b6 + jb);
    const float4* p7 = (const float4*)(g_b7 + jb);
    float4* o4 = (float4*)(out + ob);
    for (int i = threadIdx.x; i < HW/4; i += 256) {
        float4 r, a;
        float4 xv = px2[i];
        r.x = W[3]*xv.x; r.y = W[3]*xv.y; r.z = W[3]*xv.z; r.w = W[3]*xv.w;
        a = p1[i];
        r.x += W[1]*((a.x-P[0])*P[1]); r.y += W[1]*((a.y-P[0])*P[1]);
        r.z += W[1]*((a.z-P[0])*P[1]); r.w += W[1]*((a.w-P[0])*P[1]);
        a = p2[i];
        r.x += W[2]*((a.x-P[2])*P[3]); r.y += W[2]*((a.y-P[2])*P[3]);
        r.z += W[2]*((a.z-P[2])*P[3]); r.w += W[2]*((a.w-P[2])*P[3]);
        a = p4[i];
        r.x += W[4]*((a.x-P[4])*P[5]); r.y += W[4]*((a.y-P[4])*P[5]);
        r.z += W[4]*((a.z-P[4])*P[5]); r.w += W[4]*((a.w-P[4])*P[5]);
        a = p5[i];
        r.x += W[5]*((a.x-P[6])*P[7]); r.y += W[5]*((a.y-P[6])*P[7]);
        r.z += W[5]*((a.z-P[6])*P[7]); r.w += W[5]*((a.w-P[6])*P[7]);
        a = p6[i];
        r.x += W[6]*((a.x-P[8])*P[9]); r.y += W[6]*((a.y-P[8])*P[9]);
        r.z += W[6]*((a.z-P[8])*P[9]); r.w += W[6]*((a.w-P[8])*P[9]);
        a = p7[i];
        r.x += W[7]*((a.x-P[10])*P[11]); r.y += W[7]*((a.y-P[10])*P[11]);
        r.z += W[7]*((a.z-P[10])*P[11]); r.w += W[7]*((a.w-P[10])*P[11]);
        o4[i] = r;
    }
}

// ---------------- launch ----------------
extern "C" void kernel_launch(void* const* d_in, const int* in_sizes, int n_in,
                              void* d_out, int out_size) {
    const float* x    = (const float*)d_in[0];
    const float* wts  = (const float*)d_in[1];
    const float* fc1  = (const float*)d_in[2];
    const float* fc2  = (const float*)d_in[3];
    const float* saw  = (const float*)d_in[4];
    const float* s3d1 = (const float*)d_in[5];
    const float* s3p1 = (const float*)d_in[6];
    const float* s3d2 = (const float*)d_in[7];
    const float* s3p2 = (const float*)d_in[8];
    const float* s5d1 = (const float*)d_in[9];
    const float* s5p1 = (const float*)d_in[10];
    const float* s5d2 = (const float*)d_in[11];
    const float* s5p2 = (const float*)d_in[12];
    const float* d3d  = (const float*)d_in[13];
    const float* d3p  = (const float*)d_in[14];
    const float* d5d  = (const float*)d_in[15];
    const float* d5p  = (const float*)d_in[16];
    const int*   perm = (const int*)d_in[17];
    float* out = (float*)d_out;

    // Resolve real device addresses of __device__ globals (host shadow trap).
    float *p_bufA, *p_bufB, *p_b4, *p_b5, *p_b6, *p_b7, *p_WT;
    cudaGetSymbolAddress((void**)&p_bufA, g_bufA);
    cudaGetSymbolAddress((void**)&p_bufB, g_bufB);
    cudaGetSymbolAddress((void**)&p_b4,  g_b4);
    cudaGetSymbolAddress((void**)&p_b5,  g_b5);
    cudaGetSymbolAddress((void**)&p_b6,  g_b6);
    cudaGetSymbolAddress((void**)&p_b7,  g_b7);
    cudaGetSymbolAddress((void**)&p_WT,  g_WT);

    const int PW_SMEM = (CH*CH + CH*64) * (int)sizeof(float); // 96 KB
    cudaFuncSetAttribute(k_pw, cudaFuncAttributeMaxDynamicSharedMemorySize, PW_SMEM);

    k_zero_stats<<<4, 256>>>();
    k_transw<<<6, 256>>>(s3p1, s3p2, s5p1, s5p2, d3p, d5p);

    k_chanstat<<<(NB*HW)/256, 256>>>(x);
    k_saconv<<<NB*16, 256>>>(saw);
    k_x1red<<<NB*CH, 256>>>(x);
    k_att<<<NB, 128>>>(fc1, fc2);
    k_topk<<<1, 128>>>(perm);
    k_x2<<<NB*CH, 256>>>(x);

    // fused: pool (stats 0/1) + all four first-stage depthwise convs
    k_stage1<<<NB*CH, 256>>>(s3d1, s5d1, d3d, d5d);

    // sep3: pw1(bufA->b4, stats s2) -> dw2(b4->bufA, bn s2) -> pw2(bufA->b4, stats s3)
    k_pw<<<NB*64, 256, PW_SMEM>>>(p_bufA, p_WT + 0*CH*CH, p_b4, 2);
    k_dw2<3><<<NB*CH, 256>>>(p_b4, s3d2, p_bufA, 2);
    k_pw<<<NB*64, 256, PW_SMEM>>>(p_bufA, p_WT + 1*CH*CH, p_b4, 3);

    // sep5
    k_pw<<<NB*64, 256, PW_SMEM>>>(p_bufB, p_WT + 2*CH*CH, p_b5, 4);
    k_dw2<5><<<NB*CH, 256>>>(p_b5, s5d2, p_bufB, 4);
    k_pw<<<NB*64, 256, PW_SMEM>>>(p_bufB, p_WT + 3*CH*CH, p_b5, 5);

    // dil3 / dil5: pw in-place
    k_pw<<<NB*64, 256, PW_SMEM>>>(p_b6, p_WT + 4*CH*CH, p_b6, 6);
    k_pw<<<NB*64, 256, PW_SMEM>>>(p_b7, p_WT + 5*CH*CH, p_b7, 7);

    k_final<<<NB*CH, 256>>>(wts, out);
}

// round 12
// speedup vs baseline: 2.6133x; 1.6490x over previous
#include <cuda_runtime.h>
#include <cuda_bf16.h>
#include <math.h>
#include <cstdint>

#define NB 32
#define CH 128
#define HW 4096           // 64*64
#define CNT 131072.0f     // NB*HW, bn population per channel
#define EPS 1e-5f
#define SP 72             // padded plane stride (PAD=4 halo each side)
#define PPN (SP*SP)       // 5184

// ---------------- scratch (device globals; no mallocs allowed) ----------------
__device__ float g_s  [NB*2*HW];      // channel mean/max planes
__device__ float g_sig[NB*HW];        // spatial-attention sigmoid map
__device__ float g_x2 [NB*CH*HW];     // x * spatial att * channel att
__device__ float g_bufA[NB*CH*HW];    // sep3 dw / scratch
__device__ float g_bufB[NB*CH*HW];    // sep5 dw / scratch
__device__ float g_b1 [NB*CH*HW];     // maxpool branch
__device__ float g_b2 [NB*CH*HW];     // avgpool branch
__device__ float g_b4 [NB*CH*HW];     // sep3 branch
__device__ float g_b5 [NB*CH*HW];     // sep5 branch
__device__ float g_b6 [NB*CH*HW];     // dil3 branch
__device__ float g_b7 [NB*CH*HW];     // dil5 branch
__device__ float g_psum[NB*CH];
__device__ float g_pmax[NB*CH];
__device__ float g_att [NB*CH];
__device__ int   g_nd[CH];
__device__ int   g_winner[CH];
__device__ float g_sum[8*CH];         // bn stats slots
__device__ float g_sq [8*CH];

// ---------------- tiny helper kernels ----------------
__global__ void k_zero_stats() {
    int i = blockIdx.x*256 + threadIdx.x;
    if (i < 8*CH) { g_sum[i] = 0.f; g_sq[i] = 0.f; }
}

// ---------------- stage A: spatial attention ----------------
__global__ void k_chanstat(const float* __restrict__ x) {
    int idx = blockIdx.x*256 + threadIdx.x;       // n*HW + hw
    if (idx >= NB*HW) return;
    int n = idx >> 12, hw = idx & (HW-1);
    const float* p = x + (size_t)n*CH*HW + hw;
    float s = 0.f, m = -1e30f;
    #pragma unroll 8
    for (int c = 0; c < CH; c++) { float v = p[c*HW]; s += v; m = fmaxf(m, v); }
    g_s[n*2*HW + hw]      = s * (1.f/CH);
    g_s[n*2*HW + HW + hw] = m;
}

__global__ void k_saconv(const float* __restrict__ saw) {
    __shared__ float w[98];
    if (threadIdx.x < 98) w[threadIdx.x] = saw[threadIdx.x];
    __syncthreads();
    int n  = blockIdx.x >> 4;
    int hw = (blockIdx.x & 15) * 256 + threadIdx.x;
    int h = hw >> 6, wx = hw & 63;
    const float* sp = g_s + n*2*HW;
    float acc = 0.f;
    #pragma unroll
    for (int ic = 0; ic < 2; ic++)
        #pragma unroll
        for (int kh = 0; kh < 7; kh++) {
            int ih = h + kh - 3;
            if (ih < 0 || ih > 63) continue;
            #pragma unroll
            for (int kw = 0; kw < 7; kw++) {
                int iw = wx + kw - 3;
                if (iw >= 0 && iw <= 63)
                    acc += __ldg(&sp[ic*HW + ih*64 + iw]) * w[ic*49 + kh*7 + kw];
            }
        }
    g_sig[n*HW + hw] = 1.f / (1.f + __expf(-acc));
}

__global__ void k_x1red(const float* __restrict__ x) {
    int n = blockIdx.x >> 7, c = blockIdx.x & 127;
    size_t base = ((size_t)n*CH + c)*HW;
    const float* sg = g_sig + n*HW;
    float s = 0.f, m = -1e30f;
    for (int i = threadIdx.x; i < HW; i += 256) {
        float v = x[base+i] * sg[i];
        s += v; m = fmaxf(m, v);
    }
    __shared__ float rs[256], rm[256];
    rs[threadIdx.x] = s; rm[threadIdx.x] = m; __syncthreads();
    for (int o = 128; o > 0; o >>= 1) {
        if (threadIdx.x < o) {
            rs[threadIdx.x] += rs[threadIdx.x + o];
            rm[threadIdx.x] = fmaxf(rm[threadIdx.x], rm[threadIdx.x + o]);
        }
        __syncthreads();
    }
    if (threadIdx.x == 0) { g_psum[n*CH+c] = rs[0]; g_pmax[n*CH+c] = rm[0]; }
}

__global__ void k_att(const float* __restrict__ fc1, const float* __restrict__ fc2) {
    int n = blockIdx.x, t = threadIdx.x;   // 128 threads
    __shared__ float m[CH], mx[CH], hm[64], hx[64];
    m[t]  = g_psum[n*CH+t] * (1.f/HW);
    mx[t] = g_pmax[n*CH+t];
    __syncthreads();
    if (t < 64) {
        float a = 0.f, b = 0.f;
        for (int c = 0; c < CH; c++) { float w = fc1[t*CH+c]; a += w*m[c]; b += w*mx[c]; }
        hm[t] = fmaxf(a, 0.f); hx[t] = fmaxf(b, 0.f);
    }
    __syncthreads();
    float a = 0.f, b = 0.f;
    for (int k = 0; k < 64; k++) { float w = fc2[t*64+k]; a += w*hm[k]; b += w*hx[k]; }
    g_att[n*CH+t] = 1.f / (1.f + __expf(-(a + b)));
}

__global__ void k_topk(const int* __restrict__ perm) {
    int c = threadIdx.x;   // 128 threads
    __shared__ float sl[CH];
    float s = 0.f;
    for (int n = 0; n < NB; n++) s += g_att[n*CH + c];
    sl[c] = s; __syncthreads();
    float v = sl[c];
    int rank = 0;
    for (int d = 0; d < CH; d++) { float u = sl[d]; rank += (u > v) || (u == v && d < c); }
    if (rank < 96) g_nd[rank] = c;
    if (c < 32) g_nd[96 + c] = perm[c];
    int win;
    if (c < 32) {
        int inv = 0;
        for (int i = 0; i < 32; i++) if (perm[i] == c) inv = i;
        win = 96 + inv;                 // perm positions are last -> always win
    } else {
        win = (rank < 96) ? rank : -1;
    }
    g_winner[c] = win;
}

__global__ void k_x2(const float* __restrict__ x) {
    int b = blockIdx.x;     // n*CH + c
    int n = b >> 7;
    float a = g_att[b];
    const float4* sg = (const float4*)(g_sig + n*HW);
    const float4* xi = (const float4*)(x + (size_t)b*HW);
    float4*       xo = (float4*)(g_x2 + (size_t)b*HW);
    for (int i = threadIdx.x; i < HW/4; i += 256) {
        float4 v = xi[i], s = sg[i];
        v.x *= s.x*a; v.y *= s.y*a; v.z *= s.z*a; v.w *= s.w*a;
        xo[i] = v;
    }
}

// ---------------- depthwise quad helper ----------------
template<int KS, int DIL>
__device__ __forceinline__ void dw_quad(const float* __restrict__ pl, int h, int w0,
                                        const float* __restrict__ wt, float4* outv) {
    constexpr int R2 = (KS/2)*DIL;
    float a0 = 0.f, a1 = 0.f, a2 = 0.f, a3 = 0.f;
    #pragma unroll
    for (int kh = 0; kh < KS; kh++) {
        int ph = h + 4 + (kh - KS/2)*DIL;
        const float4* rp = (const float4*)&pl[ph*SP + w0];
        float buf[12];
        #pragma unroll
        for (int l = 0; l < 3; l++) {
            float4 t = rp[l];
            buf[l*4+0]=t.x; buf[l*4+1]=t.y; buf[l*4+2]=t.z; buf[l*4+3]=t.w;
        }
        #pragma unroll
        for (int kw = 0; kw < KS; kw++) {
            float wv = wt[kh*KS + kw];
            constexpr int base = 4 - R2;
            int b = base + kw*DIL;
            a0 += buf[b+0]*wv; a1 += buf[b+1]*wv; a2 += buf[b+2]*wv; a3 += buf[b+3]*wv;
        }
    }
    *outv = make_float4(a0, a1, a2, a3);
}

// ---------------- stage-1 fusion ----------------
__global__ void __launch_bounds__(256) k_stage1(
        const float* __restrict__ w3, const float* __restrict__ w5,
        const float* __restrict__ wd3, const float* __restrict__ wd5) {
    __shared__ float raw[HW];
    __shared__ float pp[PPN];
    __shared__ float red[1024];
    __shared__ float sw3[9], sw5[25], swd3[9], swd5[25];
    int n = blockIdx.x >> 7, j = blockIdx.x & 127;
    int t = threadIdx.x;
    int cin = g_nd[j];
    if (t < 9)  sw3[t]  = w3[j*9 + t];
    if (t < 25) sw5[t]  = w5[j*25 + t];
    if (t >= 32 && t < 41)  swd3[t-32] = wd3[j*9 + (t-32)];
    if (t >= 64 && t < 89)  swd5[t-64] = wd5[j*25 + (t-64)];
    for (int i = t; i < PPN/4; i += 256) ((float4*)pp)[i] = make_float4(0,0,0,0);
    __syncthreads();
    const float4* in4 = (const float4*)(g_x2 + ((size_t)n*CH + cin)*HW);
    for (int q = t; q < 1024; q += 256) {
        float4 v = in4[q];
        ((float4*)raw)[q] = v;
        int h = q >> 4, c4 = (q & 15) * 4;
        float4 r = make_float4(fmaxf(v.x,0.f), fmaxf(v.y,0.f), fmaxf(v.z,0.f), fmaxf(v.w,0.f));
        *(float4*)&pp[(h+4)*SP + c4 + 4] = r;
    }
    __syncthreads();

    size_t ob = ((size_t)n*CH + j)*HW;
    float s1 = 0.f, q1 = 0.f, s2 = 0.f, q2 = 0.f;
    for (int i = t; i < HW; i += 256) {
        int h = i >> 6, w = i & 63;
        int h0 = max(h-1,0), h1 = min(h+1,63), w0 = max(w-1,0), w1 = min(w+1,63);
        float mx = -1e30f, sm = 0.f;
        for (int hh = h0; hh <= h1; hh++)
            for (int ww = w0; ww <= w1; ww++) {
                float v = raw[hh*64+ww];
                mx = fmaxf(mx, v); sm += v;
            }
        float av = sm / (float)((h1-h0+1)*(w1-w0+1));
        g_b1[ob+i] = mx; g_b2[ob+i] = av;
        s1 += mx; q1 += mx*mx; s2 += av; q2 += av*av;
    }
    red[t] = s1; red[256+t] = q1; red[512+t] = s2; red[768+t] = q2;
    __syncthreads();
    for (int o = 128; o > 0; o >>= 1) {
        if (t < o) {
            red[t]     += red[t+o];
            red[256+t] += red[256+t+o];
            red[512+t] += red[512+t+o];
            red[768+t] += red[768+t+o];
        }
        __syncthreads();
    }
    if (t == 0) {
        atomicAdd(&g_sum[0*CH+j], red[0]);   atomicAdd(&g_sq[0*CH+j], red[256]);
        atomicAdd(&g_sum[1*CH+j], red[512]); atomicAdd(&g_sq[1*CH+j], red[768]);
    }
    for (int q = t; q < 1024; q += 256) {
        int h = q >> 4, w0 = (q & 15) * 4;
        float4 o4;
        dw_quad<3,1>(pp, h, w0, sw3,  &o4); *(float4*)&g_bufA[ob + h*64 + w0] = o4;
        dw_quad<5,1>(pp, h, w0, sw5,  &o4); *(float4*)&g_bufB[ob + h*64 + w0] = o4;
        dw_quad<3,2>(pp, h, w0, swd3, &o4); *(float4*)&g_b6 [ob + h*64 + w0] = o4;
        dw_quad<5,2>(pp, h, w0, swd5, &o4); *(float4*)&g_b7 [ob + h*64 + w0] = o4;
    }
}

// second-stage dw: in -> bn(slot)+relu -> dw(KS, dil1) -> out
template<int KS>
__global__ void __launch_bounds__(256) k_dw2(const float* __restrict__ in,
                                             const float* __restrict__ dwW,
                                             float* __restrict__ out, int slot) {
    __shared__ float pp[PPN];
    __shared__ float wt[KS*KS];
    int n = blockIdx.x >> 7, j = blockIdx.x & 127;
    int t = threadIdx.x;
    if (t < KS*KS) wt[t] = dwW[j*KS*KS + t];
    float mean = g_sum[slot*CH + j] / CNT;
    float var  = g_sq [slot*CH + j] / CNT - mean*mean;
    float rstd = rsqrtf(var + EPS);
    for (int i = t; i < PPN/4; i += 256) ((float4*)pp)[i] = make_float4(0,0,0,0);
    __syncthreads();
    const float4* in4 = (const float4*)(in + ((size_t)n*CH + j)*HW);
    for (int q = t; q < 1024; q += 256) {
        float4 v = in4[q];
        int h = q >> 4, c4 = (q & 15) * 4;
        float4 r = make_float4(fmaxf((v.x-mean)*rstd, 0.f), fmaxf((v.y-mean)*rstd, 0.f),
                               fmaxf((v.z-mean)*rstd, 0.f), fmaxf((v.w-mean)*rstd, 0.f));
        *(float4*)&pp[(h+4)*SP + c4 + 4] = r;
    }
    __syncthreads();
    size_t ob = ((size_t)n*CH + j)*HW;
    for (int q = t; q < 1024; q += 256) {
        int h = q >> 4, w0 = (q & 15) * 4;
        float4 o4;
        dw_quad<KS,1>(pp, h, w0, wt, &o4);
        *(float4*)&out[ob + h*64 + w0] = o4;
    }
}

// ---------------- tensor-core pointwise conv via mma.sync (bf16 split) ----------
// D[p,co] = sum_ci A[p,ci]*W[co,ci]; A=Ah+Al, W=Wh+Wl; D = AhWh + AhWl + AlWh.
// Block: one (n, 128-pixel tile). 8 warps = 2(m)x4(n), warp tile 64p x 32co.
#define AST 136                      // bf16 row stride (272 B)
#define TILE_B (128*AST*2)           // 34816 B per bf16 tile
#define PWM_AHI 0
#define PWM_ALO (PWM_AHI + TILE_B)
#define PWM_WHI (PWM_ALO + TILE_B)
#define PWM_WLO (PWM_WHI + TILE_B)
#define PWM_SMEM (PWM_WLO + TILE_B)  // 139264 B

__device__ __forceinline__ unsigned pk2(float a, float b, float* rla, float* rlb) {
    __nv_bfloat16 ha = __float2bfloat16(a), hb = __float2bfloat16(b);
    *rla = a - __bfloat162float(ha);
    *rlb = b - __bfloat162float(hb);
    __nv_bfloat162 v; v.x = ha; v.y = hb;
    return *(unsigned*)&v;
}
__device__ __forceinline__ unsigned pklo(float a, float b) {
    __nv_bfloat162 v; v.x = __float2bfloat16(a); v.y = __float2bfloat16(b);
    return *(unsigned*)&v;
}
__device__ __forceinline__ unsigned lds_u32(const char* base, int row, int col) {
    return *(const unsigned*)(base + row*(AST*2) + col*2);
}
__device__ __forceinline__ void mma_bf16(float* d, const unsigned* a, const unsigned* b) {
    asm volatile(
        "mma.sync.aligned.m16n8k16.row.col.f32.bf16.bf16.f32 "
        "{%0,%1,%2,%3}, {%4,%5,%6,%7}, {%8,%9}, {%0,%1,%2,%3};"
        : "+f"(d[0]), "+f"(d[1]), "+f"(d[2]), "+f"(d[3])
        : "r"(a[0]), "r"(a[1]), "r"(a[2]), "r"(a[3]), "r"(b[0]), "r"(b[1]));
}

__global__ void __launch_bounds__(256, 1)
k_pwm(const float* __restrict__ in, const float* __restrict__ wt,
      float* __restrict__ out, int slot) {
    extern __shared__ char smem[];
    int t = threadIdx.x, wid = t >> 5, lane = t & 31;
    int n = blockIdx.x >> 5;
    int pbase = (blockIdx.x & 31) << 7;

    // ---- load & split-convert: A rows=pixels, W rows=co; cols=ci ----
    for (int idx = t; idx < 2048; idx += 256) {
        int r = idx & 127, ci0 = (idx >> 7) * 8;
        uint32_t off = r*(AST*2) + ci0*2;
        {   // A
            const float* src = in + ((size_t)n*CH + ci0)*HW + pbase + r;
            float la, lb; uint4 hi, lo;
            hi.x = pk2(src[0*HW], src[1*HW], &la, &lb); lo.x = pklo(la, lb);
            hi.y = pk2(src[2*HW], src[3*HW], &la, &lb); lo.y = pklo(la, lb);
            hi.z = pk2(src[4*HW], src[5*HW], &la, &lb); lo.z = pklo(la, lb);
            hi.w = pk2(src[6*HW], src[7*HW], &la, &lb); lo.w = pklo(la, lb);
            *(uint4*)(smem + PWM_AHI + off) = hi;
            *(uint4*)(smem + PWM_ALO + off) = lo;
        }
        {   // W (original [co][ci] layout)
            const float4 wa = *(const float4*)(wt + r*CH + ci0);
            const float4 wb = *(const float4*)(wt + r*CH + ci0 + 4);
            float la, lb; uint4 hi, lo;
            hi.x = pk2(wa.x, wa.y, &la, &lb); lo.x = pklo(la, lb);
            hi.y = pk2(wa.z, wa.w, &la, &lb); lo.y = pklo(la, lb);
            hi.z = pk2(wb.x, wb.y, &la, &lb); lo.z = pklo(la, lb);
            hi.w = pk2(wb.z, wb.w, &la, &lb); lo.w = pklo(la, lb);
            *(uint4*)(smem + PWM_WHI + off) = hi;
            *(uint4*)(smem + PWM_WLO + off) = lo;
        }
    }
    __syncthreads();

    // ---- MMA: warp tile 64p x 32co ----
    int wm = wid & 1, wn = wid >> 1;
    int g = lane >> 2, tg = lane & 3;
    float d[4][4][4];
    #pragma unroll
    for (int mi = 0; mi < 4; mi++)
        #pragma unroll
        for (int ni = 0; ni < 4; ni++)
            #pragma unroll
            for (int r = 0; r < 4; r++) d[mi][ni][r] = 0.f;

    const int chainA[3] = {PWM_AHI, PWM_AHI, PWM_ALO};
    const int chainW[3] = {PWM_WHI, PWM_WLO, PWM_WHI};
    #pragma unroll
    for (int ch = 0; ch < 3; ch++) {
        const char* pA = smem + chainA[ch];
        const char* pW = smem + chainW[ch];
        #pragma unroll
        for (int k = 0; k < 8; k++) {
            int c0 = k*16 + tg*2;
            unsigned a[4][4];
            #pragma unroll
            for (int mi = 0; mi < 4; mi++) {
                int row = wm*64 + mi*16 + g;
                a[mi][0] = lds_u32(pA, row,     c0);
                a[mi][1] = lds_u32(pA, row + 8, c0);
                a[mi][2] = lds_u32(pA, row,     c0 + 8);
                a[mi][3] = lds_u32(pA, row + 8, c0 + 8);
            }
            unsigned b[4][2];
            #pragma unroll
            for (int ni = 0; ni < 4; ni++) {
                int row = wn*32 + ni*8 + g;
                b[ni][0] = lds_u32(pW, row, c0);
                b[ni][1] = lds_u32(pW, row, c0 + 8);
            }
            #pragma unroll
            for (int mi = 0; mi < 4; mi++)
                #pragma unroll
                for (int ni = 0; ni < 4; ni++)
                    mma_bf16(d[mi][ni], a[mi], b[ni]);
        }
    }
    __syncthreads();

    // ---- stage D to smem as S[co][p] (stride 132 floats), then coalesced out ----
    float* S = (float*)smem;   // 128*132*4 = 67584 B, fits in tile region
    #pragma unroll
    for (int mi = 0; mi < 4; mi++) {
        int p0 = wm*64 + mi*16 + g;
        #pragma unroll
        for (int ni = 0; ni < 4; ni++) {
            int co0 = wn*32 + ni*8 + tg*2;
            S[co0*132 + p0]          = d[mi][ni][0];
            S[(co0+1)*132 + p0]      = d[mi][ni][1];
            S[co0*132 + p0 + 8]      = d[mi][ni][2];
            S[(co0+1)*132 + p0 + 8]  = d[mi][ni][3];
        }
    }
    __syncthreads();
    {
        int co = t >> 1, p0 = (t & 1) * 64;
        const float4* src = (const float4*)(S + co*132 + p0);
        float4* dst = (float4*)(out + ((size_t)n*CH + co)*HW + pbase + p0);
        float s = 0.f, q = 0.f;
        #pragma unroll
        for (int i = 0; i < 16; i++) {
            float4 v = src[i];
            dst[i] = v;
            s += v.x + v.y + v.z + v.w;
            q += v.x*v.x + v.y*v.y + v.z*v.z + v.w*v.w;
        }
        atomicAdd(&g_sum[slot*CH + co], s);
        atomicAdd(&g_sq [slot*CH + co], q);
    }
}

// ---------------- final: weighted branch sum (+bn) and scatter ----------------
__global__ void k_final(const float* __restrict__ wts, float* __restrict__ out) {
    int n = blockIdx.x >> 7, c = blockIdx.x & 127;
    int win = g_winner[c];
    size_t ob = ((size_t)n*CH + c)*HW;
    if (win < 0) {
        float4* o4 = (float4*)(out + ob);
        const float4* x4 = (const float4*)(g_x2 + ob);
        for (int i = threadIdx.x; i < HW/4; i += 256) o4[i] = x4[i];
        return;
    }
    int j = win;
    __shared__ float P[12];
    __shared__ float W[8];
    if (threadIdx.x < 8) W[threadIdx.x] = wts[threadIdx.x];
    if (threadIdx.x == 0) {
        const int slots[6] = {0,1,3,5,6,7};
        for (int q = 0; q < 6; q++) {
            float mean = g_sum[slots[q]*CH + j] / CNT;
            float var  = g_sq [slots[q]*CH + j] / CNT - mean*mean;
            P[q*2] = mean; P[q*2+1] = rsqrtf(var + EPS);
        }
    }
    __syncthreads();
    size_t jb = ((size_t)n*CH + j)*HW;
    const float4* px2 = (const float4*)(g_x2 + ob);
    const float4* p1 = (const float4*)(g_b1 + jb);
    const float4* p2 = (const float4*)(g_b2 + jb);
    const float4* p4 = (const float4*)(g_b4 + jb);
    const float4* p5 = (const float4*)(g_b5 + jb);
    const float4* p6 = (const float4*)(g_b6 + jb);
    const float4* p7 = (const float4*)(g_b7 + jb);
    float4* o4 = (float4*)(out + ob);
    for (int i = threadIdx.x; i < HW/4; i += 256) {
        float4 r, a;
        float4 xv = px2[i];
        r.x = W[3]*xv.x; r.y = W[3]*xv.y; r.z = W[3]*xv.z; r.w = W[3]*xv.w;
        a = p1[i];
        r.x += W[1]*((a.x-P[0])*P[1]); r.y += W[1]*((a.y-P[0])*P[1]);
        r.z += W[1]*((a.z-P[0])*P[1]); r.w += W[1]*((a.w-P[0])*P[1]);
        a = p2[i];
        r.x += W[2]*((a.x-P[2])*P[3]); r.y += W[2]*((a.y-P[2])*P[3]);
        r.z += W[2]*((a.z-P[2])*P[3]); r.w += W[2]*((a.w-P[2])*P[3]);
        a = p4[i];
        r.x += W[4]*((a.x-P[4])*P[5]); r.y += W[4]*((a.y-P[4])*P[5]);
        r.z += W[4]*((a.z-P[4])*P[5]); r.w += W[4]*((a.w-P[4])*P[5]);
        a = p5[i];
        r.x += W[5]*((a.x-P[6])*P[7]); r.y += W[5]*((a.y-P[6])*P[7]);
        r.z += W[5]*((a.z-P[6])*P[7]); r.w += W[5]*((a.w-P[6])*P[7]);
        a = p6[i];
        r.x += W[6]*((a.x-P[8])*P[9]); r.y += W[6]*((a.y-P[8])*P[9]);
        r.z += W[6]*((a.z-P[8])*P[9]); r.w += W[6]*((a.w-P[8])*P[9]);
        a = p7[i];
        r.x += W[7]*((a.x-P[10])*P[11]); r.y += W[7]*((a.y-P[10])*P[11]);
        r.z += W[7]*((a.z-P[10])*P[11]); r.w += W[7]*((a.w-P[10])*P[11]);
        o4[i] = r;
    }
}

// ---------------- launch ----------------
extern "C" void kernel_launch(void* const* d_in, const int* in_sizes, int n_in,
                              void* d_out, int out_size) {
    const float* x    = (const float*)d_in[0];
    const float* wts  = (const float*)d_in[1];
    const float* fc1  = (const float*)d_in[2];
    const float* fc2  = (const float*)d_in[3];
    const float* saw  = (const float*)d_in[4];
    const float* s3d1 = (const float*)d_in[5];
    const float* s3p1 = (const float*)d_in[6];
    const float* s3d2 = (const float*)d_in[7];
    const float* s3p2 = (const float*)d_in[8];
    const float* s5d1 = (const float*)d_in[9];
    const float* s5p1 = (const float*)d_in[10];
    const float* s5d2 = (const float*)d_in[11];
    const float* s5p2 = (const float*)d_in[12];
    const float* d3d  = (const float*)d_in[13];
    const float* d3p  = (const float*)d_in[14];
    const float* d5d  = (const float*)d_in[15];
    const float* d5p  = (const float*)d_in[16];
    const int*   perm = (const int*)d_in[17];
    float* out = (float*)d_out;

    // Resolve real device addresses of __device__ globals (host shadow trap).
    float *p_bufA, *p_bufB, *p_b4, *p_b5, *p_b6, *p_b7;
    cudaGetSymbolAddress((void**)&p_bufA, g_bufA);
    cudaGetSymbolAddress((void**)&p_bufB, g_bufB);
    cudaGetSymbolAddress((void**)&p_b4,  g_b4);
    cudaGetSymbolAddress((void**)&p_b5,  g_b5);
    cudaGetSymbolAddress((void**)&p_b6,  g_b6);
    cudaGetSymbolAddress((void**)&p_b7,  g_b7);

    cudaFuncSetAttribute(k_pwm, cudaFuncAttributeMaxDynamicSharedMemorySize, PWM_SMEM);

    k_zero_stats<<<4, 256>>>();

    k_chanstat<<<(NB*HW)/256, 256>>>(x);
    k_saconv<<<NB*16, 256>>>(saw);
    k_x1red<<<NB*CH, 256>>>(x);
    k_att<<<NB, 128>>>(fc1, fc2);
    k_topk<<<1, 128>>>(perm);
    k_x2<<<NB*CH, 256>>>(x);

    // fused: pool (stats 0/1) + all four first-stage depthwise convs
    k_stage1<<<NB*CH, 256>>>(s3d1, s5d1, d3d, d5d);

    const int PWG = NB * 32;   // 1024 blocks: (n, 128-pixel tile)
    // sep3
    k_pwm<<<PWG, 256, PWM_SMEM>>>(p_bufA, s3p1, p_b4, 2);
    k_dw2<3><<<NB*CH, 256>>>(p_b4, s3d2, p_bufA, 2);
    k_pwm<<<PWG, 256, PWM_SMEM>>>(p_bufA, s3p2, p_b4, 3);
    // sep5
    k_pwm<<<PWG, 256, PWM_SMEM>>>(p_bufB, s5p1, p_b5, 4);
    k_dw2<5><<<NB*CH, 256>>>(p_b5, s5d2, p_bufB, 4);
    k_pwm<<<PWG, 256, PWM_SMEM>>>(p_bufB, s5p2, p_b5, 5);
    // dil3 / dil5: in-place (block reads its tile fully before storing)
    k_pwm<<<PWG, 256, PWM_SMEM>>>(p_b6, d3p, p_b6, 6);
    k_pwm<<<PWG, 256, PWM_SMEM>>>(p_b7, d5p, p_b7, 7);

    k_final<<<NB*CH, 256>>>(wts, out);
}